// round 15
// baseline (speedup 1.0000x reference)
#include <cuda_runtime.h>
#include <cuda_fp16.h>
#include <cstdint>

// Problem constants
#define NLAT 181
#define NLON 360
#define CIN  128
#define COUT 128
#define KS   3
#define BSZ  2
#define CHW  (NLAT * NLON)     // 65160
#define CK   (CIN * KS)        // 384
#define PT   32                // gather p-tile
#define NPT  12
#define MTOT  (BSZ * CHW)      // 130320
#define MTILE 128
#define MBLK  ((MTOT + MTILE - 1) / MTILE)   // 1019
#define MPADL (MBLK * MTILE)                 // 130432
#define ESLOT 512              // entry slots per (t,la) pair
#define NDLA  7                // la in [t-3, t+3]
#define RSLOT 128              // run slots per t
#define KCH   32               // GEMM K-chunk (halves)
#define NCH   (CK / KCH)       // 12
#define SROWB 80               // smem row stride bytes (conflict-free)
#define CHNKB (128 * SROWB)    // 10240
#define STGB  (2 * CHNKB)      // 20480 per stage (A+B)
#define NSTG  4

// Scratch (device globals — allocation-free; zero-init so padded z rows are 0)
__device__ float  g_xt[(size_t)BSZ * CHW * CIN];   // x transposed: [b][h*w][c]
__device__ float2 g_rw2[NLAT * NDLA * ESLOT];      // per-entry {w_lo, w_hi}
__device__ int4   g_runs[NLAT * RSLOT];            // {la|(s<<16), lo0, cnt_pad, wabs}
__device__ int    g_rcnt[NLAT];
__device__ __half g_zh[(size_t)MPADL * CK];        // z M-major [m][ck], fp16
__device__ __half g_wh[COUT * CK];                 // W [f][ck], fp16
__device__ double d_cosb[NLON];                    // cos(2*pi*j/359)
__device__ double d_coslat[NLAT];                  // cos(lats[i]), lats[i]=pi(180-i)/180
__device__ double d_sinlat[NLAT];

// ---------------- helpers ----------------
__device__ __forceinline__ void fma2(unsigned long long& d,
                                     unsigned long long a,
                                     unsigned long long b) {
    asm("fma.rn.f32x2 %0, %1, %2, %0;" : "+l"(d) : "l"(a), "l"(b));
}
__device__ __forceinline__ unsigned long long pack2(float x, float y) {
    unsigned long long r;
    asm("mov.b64 %0, {%1, %2};" : "=l"(r) : "f"(x), "f"(y));
    return r;
}
union F4U { float4 f; unsigned long long u[2]; };
union U2F { unsigned long long u; float2 f; };

__device__ __forceinline__ uint32_t smem_u32(const void* p) {
    uint32_t a;
    asm("{ .reg .u64 t; cvta.to.shared.u64 t, %1; cvt.u32.u64 %0, t; }"
        : "=r"(a) : "l"(p));
    return a;
}
__device__ __forceinline__ void cpasync16(uint32_t s, const void* g) {
    asm volatile("cp.async.cg.shared.global [%0], [%1], 16;" :: "r"(s), "l"(g));
}
__device__ __forceinline__ void cp_commit() {
    asm volatile("cp.async.commit_group;" ::: "memory");
}
template <int N>
__device__ __forceinline__ void cp_wait() {
    asm volatile("cp.async.wait_group %0;" :: "n"(N) : "memory");
}
__device__ __forceinline__ void mma_f16(float* d, const uint32_t* a,
                                        uint32_t b0, uint32_t b1) {
    asm volatile(
        "mma.sync.aligned.m16n8k16.row.col.f32.f16.f16.f32 "
        "{%0,%1,%2,%3}, {%4,%5,%6,%7}, {%8,%9}, {%0,%1,%2,%3};"
        : "+f"(d[0]), "+f"(d[1]), "+f"(d[2]), "+f"(d[3])
        : "r"(a[0]), "r"(a[1]), "r"(a[2]), "r"(a[3]), "r"(b0), "r"(b1));
}
__device__ __forceinline__ void ldsm_x4(uint32_t& r0, uint32_t& r1,
                                        uint32_t& r2, uint32_t& r3, uint32_t addr) {
    asm volatile("ldmatrix.sync.aligned.m8n8.x4.shared.b16 {%0,%1,%2,%3}, [%4];"
                 : "=r"(r0), "=r"(r1), "=r"(r2), "=r"(r3) : "r"(addr));
}

// ---------------------------------------------------------------------------
// Transpose x[b][c][hw] -> g_xt[b][hw][c]
// ---------------------------------------------------------------------------
__global__ void transpose_kernel(const float* __restrict__ x) {
    __shared__ float tile[32][33];
    const int hw0 = blockIdx.x * 32;
    const int c0  = blockIdx.y * 32;
    const int b   = blockIdx.z;
    const int tx = threadIdx.x, ty = threadIdx.y;
    #pragma unroll
    for (int i = 0; i < 4; i++) {
        int c  = c0 + ty + i * 8;
        int hw = hw0 + tx;
        if (hw < CHW)
            tile[ty + i * 8][tx] = x[((size_t)b * CIN + c) * CHW + hw];
    }
    __syncthreads();
    #pragma unroll
    for (int i = 0; i < 4; i++) {
        int hw = hw0 + ty + i * 8;
        int c  = c0 + tx;
        if (hw < CHW)
            g_xt[((size_t)b * CHW + hw) * CIN + c] = tile[tx][ty + i * 8];
    }
}

// W[f][ck] -> fp16 copy
__global__ void wconv_kernel(const float* __restrict__ w) {
    int i = blockIdx.x * 256 + threadIdx.x;
    if (i < COUT * CK) g_wh[i] = __float2half_rn(w[i]);
}

// fp64 trig tables
__global__ void trig_kernel() {
    const double PI = 3.141592653589793238462643383279502884;
    int i = blockIdx.x * blockDim.x + threadIdx.x;
    if (i < NLON) d_cosb[i] = cos(2.0 * PI * (double)i / 359.0);
    if (i < NLAT) {
        double l = PI * (double)(NLAT - 1 - i) / (double)(NLAT - 1);
        d_coslat[i] = cos(l);
        d_sinlat[i] = sin(l);
    }
}

// ---------------------------------------------------------------------------
// Analytic merge: warp per t, lane (0..6) per la = t-3+lane. Recomputes the
// psi geometry in closed form: u = 1-z = (1-ca*cg) + B*cos(beta), candidate
// iff u <= 1-cos(cutoff); theta = 2*asin(sqrt(u/2)) (stable at theta->0).
// Emits runs of consecutive lons with uniform hat-segment s, entry weights
// {w_lo, w_hi} (quad weight folded), zero-padded to multiples of 4.
// Boundary points carry weight ~0, so fp32/fp64 mask flips are harmless.
// ---------------------------------------------------------------------------
__global__ void merge_kernel(const float* __restrict__ qw) {
    const int t    = (blockIdx.x * blockDim.x + threadIdx.x) >> 5;
    const int lane = threadIdx.x & 31;
    if (t >= NLAT) return;

    const double PI   = 3.141592653589793238462643383279502884;
    const double CUT  = 3.0 * PI / 180.0;            // THETA_CUTOFF
    const double UCUT = 1.0 - cos(CUT);
    const float  INVD = (float)(180.0 / PI);         // 1/dtheta
    const float  INVN = (float)(1.0 / (2.0 * PI * UCUT));

    const int la = t - 3 + lane;
    const bool active = (lane < NDLA) && (la >= 0) && (la < NLAT);

    double one_mA = 0.0, B = 0.0;
    float  q = 0.f;
    if (active) {
        double ca = d_coslat[la], sa = d_sinlat[la];
        double cg = d_coslat[t],  sg = d_sinlat[t];
        one_mA = 1.0 - ca * cg;
        B      = sa * sg;
        q      = qw[la];
    }
    const int eb = (t * NDLA + lane) * ESLOT;        // fixed entry region

    int myruns = 0, rbase = 0;

    for (int pass = 0; pass < 2; pass++) {
        int runs = 0, ent = 0;
        int prevj = -2, prevs = -1, rstart = 0, rcnt = 0, rlo0 = 0;

        if (active) {
            for (int j = 0; j < NLON; j++) {
                const double u = one_mA + B * d_cosb[j];
                if (u > UCUT) {
                    if (rcnt > 0) {   // close run
                        int pad = (4 - (rcnt & 3)) & 3;
                        if (pass == 1) {
                            for (int z = 0; z < pad; z++)
                                g_rw2[eb + rstart + rcnt + z] = make_float2(0.f, 0.f);
                            int ri = rbase + runs;
                            if (ri < RSLOT)
                                g_runs[t * RSLOT + ri] =
                                    make_int4((prevs << 16) | la, rlo0,
                                              rcnt + pad, eb + rstart);
                        }
                        runs++;
                        ent = rstart + rcnt + pad;
                        rstart = ent; rcnt = 0;
                    }
                    prevj = -2; prevs = -1;
                    continue;
                }
                float uf = (float)(0.5 * u);
                if (uf < 0.f) uf = 0.f;
                const float th = 2.0f * asinf(sqrtf(uf));
                float fk = th * INVD;
                int s = (int)fk;
                if (s > 2) s = 2;
                const float f  = fk - (float)s;
                const float wl = (1.0f - f) * INVN * q;
                const float wh = (s == 2) ? 0.f : f * INVN * q;

                if (rcnt > 0 && (j != prevj + 1 || s != prevs)) {
                    int pad = (4 - (rcnt & 3)) & 3;
                    if (pass == 1) {
                        for (int z = 0; z < pad; z++)
                            g_rw2[eb + rstart + rcnt + z] = make_float2(0.f, 0.f);
                        int ri = rbase + runs;
                        if (ri < RSLOT)
                            g_runs[t * RSLOT + ri] =
                                make_int4((prevs << 16) | la, rlo0,
                                          rcnt + pad, eb + rstart);
                    }
                    runs++;
                    ent = rstart + rcnt + pad;
                    rstart = ent; rcnt = 0;
                }
                if (rcnt == 0) rlo0 = j;
                if (pass == 1 && (rstart + rcnt) < ESLOT)
                    g_rw2[eb + rstart + rcnt] = make_float2(wl, wh);
                rcnt++;
                prevj = j; prevs = s;
            }
            if (rcnt > 0) {   // close trailing run
                int pad = (4 - (rcnt & 3)) & 3;
                if (pass == 1) {
                    for (int z = 0; z < pad; z++)
                        g_rw2[eb + rstart + rcnt + z] = make_float2(0.f, 0.f);
                    int ri = rbase + runs;
                    if (ri < RSLOT)
                        g_runs[t * RSLOT + ri] =
                            make_int4((prevs << 16) | la, rlo0,
                                      rcnt + pad, eb + rstart);
                }
                runs++;
            }
        }

        if (pass == 0) {
            myruns = runs;
            int off = myruns;
            #pragma unroll
            for (int d = 1; d < 8; d <<= 1) {
                int v = __shfl_up_sync(0xffffffffu, off, d);
                if (lane >= d) off += v;
            }
            rbase = off - myruns;
            int total = __shfl_sync(0xffffffffu, off, NDLA - 1);
            if (lane == 0) g_rcnt[t] = min(total, RSLOT);
        }
    }
}

// ---------------------------------------------------------------------------
// Stage 1: gather (R14, unchanged). Per run, warp-uniform dispatch on segment
// s: 2 fma2 per entry-column for s<2, 1 for s=2. Rolling column window,
// column-ordered fma for load-latency cover. Writes z fp16 M-major.
// ---------------------------------------------------------------------------
__global__ void __launch_bounds__(256, 2)
gather_kernel() {
    const int tid  = threadIdx.x;
    const int warp = tid >> 5;
    const int lane = tid & 31;

    const int yb = blockIdx.y;
    const int t  = (yb & 1) ? (NLAT - 1 - (yb >> 1)) : (yb >> 1);   // pole-first
    const int b  = blockIdx.z;
    const int p0 = blockIdx.x * PT;
    const int pbase = p0 + warp * 4;

    const int nruns = g_rcnt[t];
    const int4* runs = g_runs + (size_t)t * RSLOT;
    const float4* xb = (const float4*)(g_xt + (size_t)b * CHW * CIN);

    unsigned long long a2[3][4][2];
    #pragma unroll
    for (int k = 0; k < 3; k++)
        #pragma unroll
        for (int q = 0; q < 4; q++) { a2[k][q][0] = 0ull; a2[k][q][1] = 0ull; }

    for (int r = 0; r < nruns; r++) {
        const int4 rn = __ldg(&runs[r]);
        const int la   = rn.x & 0xffff;
        const int s    = rn.x >> 16;
        const int cnt  = rn.z;                 // multiple of 4
        const float4* wp = (const float4*)(g_rw2 + rn.w);
        const int rowb = la * NLON;

        int col = rn.y + pbase;
        if (col >= NLON) col -= NLON;
        if (col >= NLON) col -= NLON;
        int c1 = col + 1; if (c1 >= NLON) c1 -= NLON;
        int c2 = c1 + 1;  if (c2 >= NLON) c2 -= NLON;

        F4U w0v, w1v, w2v;
        w0v.f = xb[(size_t)(rowb + col) * 32 + lane];
        w1v.f = xb[(size_t)(rowb + c1)  * 32 + lane];
        w2v.f = xb[(size_t)(rowb + c2)  * 32 + lane];
        int colx = c2;

        #define CG2(V, WL, WH, KA, KB, Q)                                         \
        {                                                                         \
            unsigned long long kk;                                                \
            kk = pack2(WL, WL);                                                   \
            fma2(a2[KA][Q][0], kk, V.u[0]); fma2(a2[KA][Q][1], kk, V.u[1]);       \
            kk = pack2(WH, WH);                                                   \
            fma2(a2[KB][Q][0], kk, V.u[0]); fma2(a2[KB][Q][1], kk, V.u[1]);       \
        }
        #define CG1(V, WL, KA, Q)                                                 \
        {                                                                         \
            unsigned long long kk = pack2(WL, WL);                                \
            fma2(a2[KA][Q][0], kk, V.u[0]); fma2(a2[KA][Q][1], kk, V.u[1]);       \
        }
        #define RUN_LOOP2(KA, KB)                                                 \
        for (int j4 = 0; j4 < cnt; j4 += 4) {                                     \
            int n0 = colx + 1; if (n0 >= NLON) n0 -= NLON;                        \
            int n1 = colx + 2; if (n1 >= NLON) n1 -= NLON;                        \
            int n2 = colx + 3; if (n2 >= NLON) n2 -= NLON;                        \
            int n3 = colx + 4; if (n3 >= NLON) n3 -= NLON;                        \
            colx = n3;                                                            \
            F4U nw0, nw1, nw2, nw3;                                               \
            nw0.f = xb[(size_t)(rowb + n0) * 32 + lane];                          \
            nw1.f = xb[(size_t)(rowb + n1) * 32 + lane];                          \
            nw2.f = xb[(size_t)(rowb + n2) * 32 + lane];                          \
            nw3.f = xb[(size_t)(rowb + n3) * 32 + lane];                          \
            float4 fa = __ldg(&wp[j4 >> 1]);                                      \
            float4 fb = __ldg(&wp[(j4 >> 1) + 1]);                                \
            CG2(w0v, fa.x, fa.y, KA, KB, 0)                                       \
            CG2(w1v, fa.x, fa.y, KA, KB, 1) CG2(w1v, fa.z, fa.w, KA, KB, 0)       \
            CG2(w2v, fa.x, fa.y, KA, KB, 2) CG2(w2v, fa.z, fa.w, KA, KB, 1)       \
            CG2(w2v, fb.x, fb.y, KA, KB, 0)                                       \
            CG2(nw0, fa.x, fa.y, KA, KB, 3) CG2(nw0, fa.z, fa.w, KA, KB, 2)       \
            CG2(nw0, fb.x, fb.y, KA, KB, 1) CG2(nw0, fb.z, fb.w, KA, KB, 0)       \
            CG2(nw1, fa.z, fa.w, KA, KB, 3) CG2(nw1, fb.x, fb.y, KA, KB, 2)       \
            CG2(nw1, fb.z, fb.w, KA, KB, 1)                                       \
            CG2(nw2, fb.x, fb.y, KA, KB, 3) CG2(nw2, fb.z, fb.w, KA, KB, 2)       \
            CG2(nw3, fb.z, fb.w, KA, KB, 3)                                       \
            w0v = nw1; w1v = nw2; w2v = nw3;                                      \
        }
        #define RUN_LOOP1(KA)                                                     \
        for (int j4 = 0; j4 < cnt; j4 += 4) {                                     \
            int n0 = colx + 1; if (n0 >= NLON) n0 -= NLON;                        \
            int n1 = colx + 2; if (n1 >= NLON) n1 -= NLON;                        \
            int n2 = colx + 3; if (n2 >= NLON) n2 -= NLON;                        \
            int n3 = colx + 4; if (n3 >= NLON) n3 -= NLON;                        \
            colx = n3;                                                            \
            F4U nw0, nw1, nw2, nw3;                                               \
            nw0.f = xb[(size_t)(rowb + n0) * 32 + lane];                          \
            nw1.f = xb[(size_t)(rowb + n1) * 32 + lane];                          \
            nw2.f = xb[(size_t)(rowb + n2) * 32 + lane];                          \
            nw3.f = xb[(size_t)(rowb + n3) * 32 + lane];                          \
            float4 fa = __ldg(&wp[j4 >> 1]);                                      \
            float4 fb = __ldg(&wp[(j4 >> 1) + 1]);                                \
            CG1(w0v, fa.x, KA, 0)                                                 \
            CG1(w1v, fa.x, KA, 1) CG1(w1v, fa.z, KA, 0)                           \
            CG1(w2v, fa.x, KA, 2) CG1(w2v, fa.z, KA, 1) CG1(w2v, fb.x, KA, 0)     \
            CG1(nw0, fa.x, KA, 3) CG1(nw0, fa.z, KA, 2) CG1(nw0, fb.x, KA, 1)     \
            CG1(nw0, fb.z, KA, 0)                                                 \
            CG1(nw1, fa.z, KA, 3) CG1(nw1, fb.x, KA, 2) CG1(nw1, fb.z, KA, 1)     \
            CG1(nw2, fb.x, KA, 3) CG1(nw2, fb.z, KA, 2)                           \
            CG1(nw3, fb.z, KA, 3)                                                 \
            w0v = nw1; w1v = nw2; w2v = nw3;                                      \
        }

        if (s == 0)      { RUN_LOOP2(0, 1) }
        else if (s == 1) { RUN_LOOP2(1, 2) }
        else             { RUN_LOOP1(2) }

        #undef RUN_LOOP2
        #undef RUN_LOOP1
        #undef CG2
        #undef CG1
    }

    // store z[m][ck] as fp16: ck = (lane*4 + c)*3 + k, 12 halves per q
    if (pbase < NLON) {
        const size_t mb = (size_t)(b * NLAT + t) * NLON + pbase;
        #pragma unroll
        for (int q = 0; q < 4; q++) {
            __half2* zp = (__half2*)(g_zh + (mb + q) * (size_t)CK + lane * 12);
            U2F c0k0, c0k1, c0k2, c1k0, c1k1, c1k2;
            c0k0.u = a2[0][q][0]; c0k1.u = a2[1][q][0]; c0k2.u = a2[2][q][0];
            c1k0.u = a2[0][q][1]; c1k1.u = a2[1][q][1]; c1k2.u = a2[2][q][1];
            zp[0] = __floats2half2_rn(c0k0.f.x, c0k1.f.x);
            zp[1] = __floats2half2_rn(c0k2.f.x, c0k0.f.y);
            zp[2] = __floats2half2_rn(c0k1.f.y, c0k2.f.y);
            zp[3] = __floats2half2_rn(c1k0.f.x, c1k1.f.x);
            zp[4] = __floats2half2_rn(c1k2.f.x, c1k0.f.y);
            zp[5] = __floats2half2_rn(c1k1.f.y, c1k2.f.y);
        }
    }
}

// ---------------------------------------------------------------------------
// Stage 2: fp16 mma.sync m16n8k16 GEMM, 4-stage cp.async pipeline (R14).
// ---------------------------------------------------------------------------
__global__ void __launch_bounds__(256, 2)
gemm_mma_kernel(const float* __restrict__ bias, float* __restrict__ out) {
    extern __shared__ __align__(16) char smem[];     // [NSTG][STGB]
    __shared__ float s_bias[COUT];

    const int tid  = threadIdx.x;
    const int warp = tid >> 5;
    const int lane = tid & 31;
    const int g    = lane >> 2;
    const int tg   = lane & 3;
    const int wm   = warp & 3;
    const int wn   = warp >> 2;
    const int m0   = blockIdx.x * MTILE;

    const uint32_t sbase = smem_u32(smem);
    const int lrw = tid >> 1;
    const int lsg = (tid & 1) * 2;

    if (tid < COUT) s_bias[tid] = __ldg(bias + tid);

    const uint32_t lrow = (uint32_t)(lane & 15);
    const uint32_t lsel = (uint32_t)(lane >> 4) * 16;
    uint32_t a_adr[2], b_adr[4];
    #pragma unroll
    for (int mt = 0; mt < 2; mt++)
        a_adr[mt] = sbase + (wm * 32 + mt * 16 + lrow) * SROWB + lsel;
    #pragma unroll
    for (int pr = 0; pr < 4; pr++)
        b_adr[pr] = sbase + CHNKB + (wn * 64 + pr * 16 + lrow) * SROWB + lsel;

    float acc[2][8][4];
    #pragma unroll
    for (int mt = 0; mt < 2; mt++)
        #pragma unroll
        for (int nt = 0; nt < 8; nt++)
            #pragma unroll
            for (int i = 0; i < 4; i++) acc[mt][nt][i] = 0.f;

    #define LOAD_CHUNK(CH, BUFI)                                                   \
    {                                                                              \
        const uint32_t sa = sbase + (uint32_t)(BUFI) * STGB;                       \
        _Pragma("unroll")                                                          \
        for (int s = 0; s < 2; s++) {                                              \
            const int seg = lsg + s;                                               \
            const uint32_t so = (uint32_t)(lrw * SROWB + seg * 16);                \
            cpasync16(sa + so, &g_zh[(size_t)(m0 + lrw) * CK + (CH) * KCH + seg * 8]); \
            cpasync16(sa + CHNKB + so, &g_wh[lrw * CK + (CH) * KCH + seg * 8]);    \
        }                                                                          \
        cp_commit();                                                               \
    }

    LOAD_CHUNK(0, 0)
    LOAD_CHUNK(1, 1)
    LOAD_CHUNK(2, 2)

    for (int ch = 0; ch < NCH; ch++) {
        if (ch + 2 < NCH)      cp_wait<2>();
        else if (ch + 1 < NCH) cp_wait<1>();
        else                   cp_wait<0>();
        __syncthreads();
        if (ch + 3 < NCH) { LOAD_CHUNK(ch + 3, (ch + 3) % NSTG) }

        const uint32_t bufo = (uint32_t)(ch % NSTG) * STGB;
        #pragma unroll
        for (int ksk = 0; ksk < 2; ksk++) {
            const uint32_t ko = bufo + ksk * 32;
            uint32_t afr[2][4];
            #pragma unroll
            for (int mt = 0; mt < 2; mt++)
                ldsm_x4(afr[mt][0], afr[mt][1], afr[mt][2], afr[mt][3],
                        a_adr[mt] + ko);
            #pragma unroll
            for (int pr = 0; pr < 4; pr++) {
                uint32_t r0, r1, r2, r3;
                ldsm_x4(r0, r1, r2, r3, b_adr[pr] + ko);
                mma_f16(acc[0][2 * pr],     afr[0], r0, r2);
                mma_f16(acc[1][2 * pr],     afr[1], r0, r2);
                mma_f16(acc[0][2 * pr + 1], afr[0], r1, r3);
                mma_f16(acc[1][2 * pr + 1], afr[1], r1, r3);
            }
        }
    }

    #pragma unroll
    for (int mt = 0; mt < 2; mt++) {
        const int mlo = m0 + wm * 32 + mt * 16 + g;
        const int mhi = mlo + 8;
        const bool vlo = (mlo < MTOT), vhi = (mhi < MTOT);
        float* plo = nullptr;
        float* phi = nullptr;
        if (vlo) { int bb = mlo / CHW; plo = out + (size_t)bb * COUT * CHW + (mlo - bb * CHW); }
        if (vhi) { int bb = mhi / CHW; phi = out + (size_t)bb * COUT * CHW + (mhi - bb * CHW); }
        #pragma unroll
        for (int nt = 0; nt < 8; nt++) {
            const int f0 = wn * 64 + nt * 8 + tg * 2;
            const float b0 = s_bias[f0], b1 = s_bias[f0 + 1];
            if (vlo) {
                plo[(size_t)f0 * CHW]       = acc[mt][nt][0] + b0;
                plo[(size_t)(f0 + 1) * CHW] = acc[mt][nt][1] + b1;
            }
            if (vhi) {
                phi[(size_t)f0 * CHW]       = acc[mt][nt][2] + b0;
                phi[(size_t)(f0 + 1) * CHW] = acc[mt][nt][3] + b1;
            }
        }
    }
    #undef LOAD_CHUNK
}

// ---------------------------------------------------------------------------
// Launch.
// ---------------------------------------------------------------------------
extern "C" void kernel_launch(void* const* d_in, const int* in_sizes, int n_in,
                              void* d_out, int out_size) {
    const float* x      = (const float*)d_in[0];
    const float* qw     = (const float*)d_in[1];
    const float* weight = (const float*)d_in[3];
    const float* bias   = (const float*)d_in[4];

    trig_kernel<<<2, 256>>>();
    dim3 tgrid((CHW + 31) / 32, CIN / 32, BSZ);
    transpose_kernel<<<tgrid, dim3(32, 8)>>>(x);
    wconv_kernel<<<(COUT * CK + 255) / 256, 256>>>(weight);
    merge_kernel<<<(NLAT * 32 + 127) / 128, 128>>>(qw);

    dim3 ggrid(NPT, NLAT, BSZ);
    gather_kernel<<<ggrid, 256>>>();

    const int dyn_bytes = NSTG * STGB;   // 81920
    cudaFuncSetAttribute(gemm_mma_kernel,
                         cudaFuncAttributeMaxDynamicSharedMemorySize, dyn_bytes);
    gemm_mma_kernel<<<MBLK, 256, dyn_bytes>>>(bias, (float*)d_out);
}

// round 16
// speedup vs baseline: 1.4961x; 1.4961x over previous
#include <cuda_runtime.h>
#include <cuda_fp16.h>
#include <cstdint>

// Problem constants
#define NLAT 181
#define NLON 360
#define CIN  128
#define COUT 128
#define KS   3
#define BSZ  2
#define CHW  (NLAT * NLON)     // 65160
#define CK   (CIN * KS)        // 384
#define PT   32                // gather p-tile
#define NPT  12
#define MTOT  (BSZ * CHW)      // 130320
#define MTILE 128
#define MBLK  ((MTOT + MTILE - 1) / MTILE)   // 1019
#define MPADL (MBLK * MTILE)                 // 130432
#define NDLA  7                // la in [t-3, t+3]
#define NPAIR (NLAT * NDLA)    // 1267
#define MAXR  12               // run slots per (t,dla)
#define KCH   32               // GEMM K-chunk (halves)
#define NCH   (CK / KCH)       // 12
#define SROWB 80               // smem row stride bytes (conflict-free)
#define CHNKB (128 * SROWB)    // 10240
#define STGB  (2 * CHNKB)      // 20480 per stage (A+B)
#define NSTG  4

// Scratch (device globals — allocation-free; zero-init so padded z rows are 0)
__device__ float   g_xt[(size_t)BSZ * CHW * CIN];   // x transposed: [b][h*w][c]
__device__ float2  g_rw2[NPAIR * NLON];             // j-indexed {w_lo, w_hi}
__device__ uint8_t g_code[NPAIR * NLON];            // 0=invalid, else s+1
__device__ int4    g_runs[NPAIR * MAXR];            // {la|(s<<16), j0, cnt, wabs}
__device__ int     g_rcnt[NPAIR];
__device__ __half  g_zh[(size_t)MPADL * CK];        // z M-major [m][ck], fp16
__device__ __half  g_wh[COUT * CK];                 // W [f][ck], fp16
__device__ double  d_cosb[NLON];
__device__ double  d_coslat[NLAT];
__device__ double  d_sinlat[NLAT];

// ---------------- helpers ----------------
__device__ __forceinline__ void fma2(unsigned long long& d,
                                     unsigned long long a,
                                     unsigned long long b) {
    asm("fma.rn.f32x2 %0, %1, %2, %0;" : "+l"(d) : "l"(a), "l"(b));
}
__device__ __forceinline__ unsigned long long pack2(float x, float y) {
    unsigned long long r;
    asm("mov.b64 %0, {%1, %2};" : "=l"(r) : "f"(x), "f"(y));
    return r;
}
union F4U { float4 f; unsigned long long u[2]; };
union U2F { unsigned long long u; float2 f; };

__device__ __forceinline__ uint32_t smem_u32(const void* p) {
    uint32_t a;
    asm("{ .reg .u64 t; cvta.to.shared.u64 t, %1; cvt.u32.u64 %0, t; }"
        : "=r"(a) : "l"(p));
    return a;
}
__device__ __forceinline__ void cpasync16(uint32_t s, const void* g) {
    asm volatile("cp.async.cg.shared.global [%0], [%1], 16;" :: "r"(s), "l"(g));
}
__device__ __forceinline__ void cp_commit() {
    asm volatile("cp.async.commit_group;" ::: "memory");
}
template <int N>
__device__ __forceinline__ void cp_wait() {
    asm volatile("cp.async.wait_group %0;" :: "n"(N) : "memory");
}
__device__ __forceinline__ void mma_f16(float* d, const uint32_t* a,
                                        uint32_t b0, uint32_t b1) {
    asm volatile(
        "mma.sync.aligned.m16n8k16.row.col.f32.f16.f16.f32 "
        "{%0,%1,%2,%3}, {%4,%5,%6,%7}, {%8,%9}, {%0,%1,%2,%3};"
        : "+f"(d[0]), "+f"(d[1]), "+f"(d[2]), "+f"(d[3])
        : "r"(a[0]), "r"(a[1]), "r"(a[2]), "r"(a[3]), "r"(b0), "r"(b1));
}
__device__ __forceinline__ void ldsm_x4(uint32_t& r0, uint32_t& r1,
                                        uint32_t& r2, uint32_t& r3, uint32_t addr) {
    asm volatile("ldmatrix.sync.aligned.m8n8.x4.shared.b16 {%0,%1,%2,%3}, [%4];"
                 : "=r"(r0), "=r"(r1), "=r"(r2), "=r"(r3) : "r"(addr));
}

// ---------------------------------------------------------------------------
// Transpose x[b][c][hw] -> g_xt[b][hw][c]
// ---------------------------------------------------------------------------
__global__ void transpose_kernel(const float* __restrict__ x) {
    __shared__ float tile[32][33];
    const int hw0 = blockIdx.x * 32;
    const int c0  = blockIdx.y * 32;
    const int b   = blockIdx.z;
    const int tx = threadIdx.x, ty = threadIdx.y;
    #pragma unroll
    for (int i = 0; i < 4; i++) {
        int c  = c0 + ty + i * 8;
        int hw = hw0 + tx;
        if (hw < CHW)
            tile[ty + i * 8][tx] = x[((size_t)b * CIN + c) * CHW + hw];
    }
    __syncthreads();
    #pragma unroll
    for (int i = 0; i < 4; i++) {
        int hw = hw0 + ty + i * 8;
        int c  = c0 + tx;
        if (hw < CHW)
            g_xt[((size_t)b * CHW + hw) * CIN + c] = tile[tx][ty + i * 8];
    }
}

// W[f][ck] -> fp16 copy
__global__ void wconv_kernel(const float* __restrict__ w) {
    int i = blockIdx.x * 256 + threadIdx.x;
    if (i < COUT * CK) g_wh[i] = __float2half_rn(w[i]);
}

// fp64 trig tables
__global__ void trig_kernel() {
    const double PI = 3.141592653589793238462643383279502884;
    int i = blockIdx.x * blockDim.x + threadIdx.x;
    if (i < NLON) d_cosb[i] = cos(2.0 * PI * (double)i / 359.0);
    if (i < NLAT) {
        double l = PI * (double)(NLAT - 1 - i) / (double)(NLAT - 1);
        d_coslat[i] = cos(l);
        d_sinlat[i] = sin(l);
    }
}

// ---------------------------------------------------------------------------
// Phase A: one thread per (t,dla,j). Analytic psi weights (validated in R15):
// u = (1-ca*cg) + B*cosb; candidate iff u <= 1-cos(cutoff);
// theta = 2*asin(sqrt(u/2)). Stores j-indexed weights + segment code.
// ---------------------------------------------------------------------------
__global__ void wcomp_kernel(const float* __restrict__ qw) {
    const int i = blockIdx.x * blockDim.x + threadIdx.x;
    if (i >= NPAIR * NLON) return;
    const int j    = i % NLON;
    const int rest = i / NLON;
    const int dla  = rest % NDLA;
    const int t    = rest / NDLA;
    const int la   = t - 3 + dla;

    const double PI   = 3.141592653589793238462643383279502884;
    const double CUT  = 3.0 * PI / 180.0;
    const double UCUT = 1.0 - cos(CUT);
    const float  INVD = (float)(180.0 / PI);
    const float  INVN = (float)(1.0 / (2.0 * PI * UCUT));

    uint8_t code = 0;
    float2  w = make_float2(0.f, 0.f);
    if (la >= 0 && la < NLAT) {
        const double u = (1.0 - d_coslat[la] * d_coslat[t])
                       + d_sinlat[la] * d_sinlat[t] * d_cosb[j];
        if (u <= UCUT) {
            float uf = (float)(0.5 * u);
            if (uf < 0.f) uf = 0.f;
            const float th = 2.0f * asinf(sqrtf(uf));
            float fk = th * INVD;
            int s = (int)fk;
            if (s > 2) s = 2;
            const float f = fk - (float)s;
            const float q = qw[la];
            w.x = (1.0f - f) * INVN * q;
            w.y = (s == 2) ? 0.f : f * INVN * q;
            code = (uint8_t)(s + 1);
        }
    }
    g_rw2[i]  = w;
    g_code[i] = code;
}

// ---------------------------------------------------------------------------
// Phase B: one thread per (t,dla). Scan 360 codes, emit runs of consecutive
// lons with uniform segment: {la|(s<<16), j0, cnt_exact, wabs=base+j0}.
// ---------------------------------------------------------------------------
__global__ void runs_kernel() {
    const int idx = blockIdx.x * blockDim.x + threadIdx.x;
    if (idx >= NPAIR) return;
    const int t   = idx / NDLA;
    const int dla = idx % NDLA;
    const int la  = t - 3 + dla;

    int nr = 0;
    if (la >= 0 && la < NLAT) {
        const uint8_t* code = g_code + (size_t)idx * NLON;
        int prev = 0, start = 0;
        #pragma unroll 4
        for (int j = 0; j < NLON; j++) {
            const int c = code[j];
            if (c != prev) {
                if (prev != 0 && nr < MAXR)
                    g_runs[idx * MAXR + nr++] =
                        make_int4(((prev - 1) << 16) | la, start,
                                  j - start, idx * NLON + start);
                if (c != 0) start = j;
                prev = c;
            }
        }
        if (prev != 0 && nr < MAXR)
            g_runs[idx * MAXR + nr++] =
                make_int4(((prev - 1) << 16) | la, start,
                          NLON - start, idx * NLON + start);
    }
    g_rcnt[idx] = nr;
}

// ---------------------------------------------------------------------------
// Stage 1: gather. Per run, warp-uniform dispatch on segment s (2 fma2 per
// entry-column for s<2, 1 for s=2). Rolling column window, column-ordered fma
// for load-latency cover; exact counts with <=3-entry tail. z fp16 M-major.
// ---------------------------------------------------------------------------
__global__ void __launch_bounds__(256, 2)
gather_kernel() {
    const int tid  = threadIdx.x;
    const int warp = tid >> 5;
    const int lane = tid & 31;

    const int yb = blockIdx.y;
    const int t  = (yb & 1) ? (NLAT - 1 - (yb >> 1)) : (yb >> 1);   // pole-first
    const int b  = blockIdx.z;
    const int p0 = blockIdx.x * PT;
    const int pbase = p0 + warp * 4;

    const float4* xb = (const float4*)(g_xt + (size_t)b * CHW * CIN);

    unsigned long long a2[3][4][2];
    #pragma unroll
    for (int k = 0; k < 3; k++)
        #pragma unroll
        for (int q = 0; q < 4; q++) { a2[k][q][0] = 0ull; a2[k][q][1] = 0ull; }

    for (int dla = 0; dla < NDLA; dla++) {
        const int pidx = t * NDLA + dla;
        const int nr = g_rcnt[pidx];
        for (int rr = 0; rr < nr; rr++) {
            const int4 rn = __ldg(&g_runs[pidx * MAXR + rr]);
            const int la  = rn.x & 0xffff;
            const int s   = rn.x >> 16;
            const int cnt = rn.z;                  // exact
            const float2* wp2 = (const float2*)g_rw2 + rn.w;
            const int rowb = la * NLON;

            int col = rn.y + pbase;
            if (col >= NLON) col -= NLON;
            if (col >= NLON) col -= NLON;
            int c1 = col + 1; if (c1 >= NLON) c1 -= NLON;
            int c2 = c1 + 1;  if (c2 >= NLON) c2 -= NLON;

            F4U w0v, w1v, w2v;
            w0v.f = xb[(size_t)(rowb + col) * 32 + lane];
            w1v.f = xb[(size_t)(rowb + c1)  * 32 + lane];
            w2v.f = xb[(size_t)(rowb + c2)  * 32 + lane];
            int colx = c2;

            const int cnt4 = cnt & ~3;
            const int rem  = cnt & 3;

            #define CGW2(V, WE, KA, KB, Q)                                        \
            {                                                                     \
                unsigned long long kk;                                            \
                kk = pack2(WE.x, WE.x);                                           \
                fma2(a2[KA][Q][0], kk, V.u[0]); fma2(a2[KA][Q][1], kk, V.u[1]);   \
                kk = pack2(WE.y, WE.y);                                           \
                fma2(a2[KB][Q][0], kk, V.u[0]); fma2(a2[KB][Q][1], kk, V.u[1]);   \
            }
            #define CGW1(V, WE, KA, Q)                                            \
            {                                                                     \
                unsigned long long kk = pack2(WE.x, WE.x);                        \
                fma2(a2[KA][Q][0], kk, V.u[0]); fma2(a2[KA][Q][1], kk, V.u[1]);   \
            }
            #define MAIN_LOOP(CGX, ...)                                           \
            for (int j4 = 0; j4 < cnt4; j4 += 4) {                                \
                int n0 = colx + 1; if (n0 >= NLON) n0 -= NLON;                    \
                int n1 = colx + 2; if (n1 >= NLON) n1 -= NLON;                    \
                int n2 = colx + 3; if (n2 >= NLON) n2 -= NLON;                    \
                int n3 = colx + 4; if (n3 >= NLON) n3 -= NLON;                    \
                colx = n3;                                                        \
                F4U nw0, nw1, nw2, nw3;                                           \
                nw0.f = xb[(size_t)(rowb + n0) * 32 + lane];                      \
                nw1.f = xb[(size_t)(rowb + n1) * 32 + lane];                      \
                nw2.f = xb[(size_t)(rowb + n2) * 32 + lane];                      \
                nw3.f = xb[(size_t)(rowb + n3) * 32 + lane];                      \
                const float2 we0 = __ldg(&wp2[j4 + 0]);                           \
                const float2 we1 = __ldg(&wp2[j4 + 1]);                           \
                const float2 we2 = __ldg(&wp2[j4 + 2]);                           \
                const float2 we3 = __ldg(&wp2[j4 + 3]);                           \
                CGX(w0v, we0, __VA_ARGS__, 0)                                     \
                CGX(w1v, we0, __VA_ARGS__, 1) CGX(w1v, we1, __VA_ARGS__, 0)       \
                CGX(w2v, we0, __VA_ARGS__, 2) CGX(w2v, we1, __VA_ARGS__, 1)       \
                CGX(w2v, we2, __VA_ARGS__, 0)                                     \
                CGX(nw0, we0, __VA_ARGS__, 3) CGX(nw0, we1, __VA_ARGS__, 2)       \
                CGX(nw0, we2, __VA_ARGS__, 1) CGX(nw0, we3, __VA_ARGS__, 0)       \
                CGX(nw1, we1, __VA_ARGS__, 3) CGX(nw1, we2, __VA_ARGS__, 2)       \
                CGX(nw1, we3, __VA_ARGS__, 1)                                     \
                CGX(nw2, we2, __VA_ARGS__, 3) CGX(nw2, we3, __VA_ARGS__, 2)       \
                CGX(nw3, we3, __VA_ARGS__, 3)                                     \
                w0v = nw1; w1v = nw2; w2v = nw3;                                  \
            }
            #define TAIL_LOOP(CGX, ...)                                           \
            for (int e = 0; e < rem; e++) {                                       \
                int nc = colx + 1; if (nc >= NLON) nc -= NLON;                    \
                colx = nc;                                                        \
                F4U nw;                                                           \
                nw.f = xb[(size_t)(rowb + nc) * 32 + lane];                       \
                const float2 we = __ldg(&wp2[cnt4 + e]);                          \
                CGX(w0v, we, __VA_ARGS__, 0)                                      \
                CGX(w1v, we, __VA_ARGS__, 1)                                      \
                CGX(w2v, we, __VA_ARGS__, 2)                                      \
                CGX(nw,  we, __VA_ARGS__, 3)                                      \
                w0v = w1v; w1v = w2v; w2v = nw;                                   \
            }

            if (s == 0)      { MAIN_LOOP(CGW2, 0, 1) TAIL_LOOP(CGW2, 0, 1) }
            else if (s == 1) { MAIN_LOOP(CGW2, 1, 2) TAIL_LOOP(CGW2, 1, 2) }
            else             { MAIN_LOOP(CGW1, 2)    TAIL_LOOP(CGW1, 2) }

            #undef MAIN_LOOP
            #undef TAIL_LOOP
            #undef CGW2
            #undef CGW1
        }
    }

    // store z[m][ck] as fp16: ck = (lane*4 + c)*3 + k, 12 halves per q
    if (pbase < NLON) {
        const size_t mb = (size_t)(b * NLAT + t) * NLON + pbase;
        #pragma unroll
        for (int q = 0; q < 4; q++) {
            __half2* zp = (__half2*)(g_zh + (mb + q) * (size_t)CK + lane * 12);
            U2F c0k0, c0k1, c0k2, c1k0, c1k1, c1k2;
            c0k0.u = a2[0][q][0]; c0k1.u = a2[1][q][0]; c0k2.u = a2[2][q][0];
            c1k0.u = a2[0][q][1]; c1k1.u = a2[1][q][1]; c1k2.u = a2[2][q][1];
            zp[0] = __floats2half2_rn(c0k0.f.x, c0k1.f.x);
            zp[1] = __floats2half2_rn(c0k2.f.x, c0k0.f.y);
            zp[2] = __floats2half2_rn(c0k1.f.y, c0k2.f.y);
            zp[3] = __floats2half2_rn(c1k0.f.x, c1k1.f.x);
            zp[4] = __floats2half2_rn(c1k2.f.x, c1k0.f.y);
            zp[5] = __floats2half2_rn(c1k1.f.y, c1k2.f.y);
        }
    }
}

// ---------------------------------------------------------------------------
// Stage 2: fp16 mma.sync m16n8k16 GEMM, 4-stage cp.async pipeline (R14).
// ---------------------------------------------------------------------------
__global__ void __launch_bounds__(256, 2)
gemm_mma_kernel(const float* __restrict__ bias, float* __restrict__ out) {
    extern __shared__ __align__(16) char smem[];     // [NSTG][STGB]
    __shared__ float s_bias[COUT];

    const int tid  = threadIdx.x;
    const int warp = tid >> 5;
    const int lane = tid & 31;
    const int g    = lane >> 2;
    const int tg   = lane & 3;
    const int wm   = warp & 3;
    const int wn   = warp >> 2;
    const int m0   = blockIdx.x * MTILE;

    const uint32_t sbase = smem_u32(smem);
    const int lrw = tid >> 1;
    const int lsg = (tid & 1) * 2;

    if (tid < COUT) s_bias[tid] = __ldg(bias + tid);

    const uint32_t lrow = (uint32_t)(lane & 15);
    const uint32_t lsel = (uint32_t)(lane >> 4) * 16;
    uint32_t a_adr[2], b_adr[4];
    #pragma unroll
    for (int mt = 0; mt < 2; mt++)
        a_adr[mt] = sbase + (wm * 32 + mt * 16 + lrow) * SROWB + lsel;
    #pragma unroll
    for (int pr = 0; pr < 4; pr++)
        b_adr[pr] = sbase + CHNKB + (wn * 64 + pr * 16 + lrow) * SROWB + lsel;

    float acc[2][8][4];
    #pragma unroll
    for (int mt = 0; mt < 2; mt++)
        #pragma unroll
        for (int nt = 0; nt < 8; nt++)
            #pragma unroll
            for (int i = 0; i < 4; i++) acc[mt][nt][i] = 0.f;

    #define LOAD_CHUNK(CH, BUFI)                                                   \
    {                                                                              \
        const uint32_t sa = sbase + (uint32_t)(BUFI) * STGB;                       \
        _Pragma("unroll")                                                          \
        for (int s = 0; s < 2; s++) {                                              \
            const int seg = lsg + s;                                               \
            const uint32_t so = (uint32_t)(lrw * SROWB + seg * 16);                \
            cpasync16(sa + so, &g_zh[(size_t)(m0 + lrw) * CK + (CH) * KCH + seg * 8]); \
            cpasync16(sa + CHNKB + so, &g_wh[lrw * CK + (CH) * KCH + seg * 8]);    \
        }                                                                          \
        cp_commit();                                                               \
    }

    LOAD_CHUNK(0, 0)
    LOAD_CHUNK(1, 1)
    LOAD_CHUNK(2, 2)

    for (int ch = 0; ch < NCH; ch++) {
        if (ch + 2 < NCH)      cp_wait<2>();
        else if (ch + 1 < NCH) cp_wait<1>();
        else                   cp_wait<0>();
        __syncthreads();
        if (ch + 3 < NCH) { LOAD_CHUNK(ch + 3, (ch + 3) % NSTG) }

        const uint32_t bufo = (uint32_t)(ch % NSTG) * STGB;
        #pragma unroll
        for (int ksk = 0; ksk < 2; ksk++) {
            const uint32_t ko = bufo + ksk * 32;
            uint32_t afr[2][4];
            #pragma unroll
            for (int mt = 0; mt < 2; mt++)
                ldsm_x4(afr[mt][0], afr[mt][1], afr[mt][2], afr[mt][3],
                        a_adr[mt] + ko);
            #pragma unroll
            for (int pr = 0; pr < 4; pr++) {
                uint32_t r0, r1, r2, r3;
                ldsm_x4(r0, r1, r2, r3, b_adr[pr] + ko);
                mma_f16(acc[0][2 * pr],     afr[0], r0, r2);
                mma_f16(acc[1][2 * pr],     afr[1], r0, r2);
                mma_f16(acc[0][2 * pr + 1], afr[0], r1, r3);
                mma_f16(acc[1][2 * pr + 1], afr[1], r1, r3);
            }
        }
    }

    #pragma unroll
    for (int mt = 0; mt < 2; mt++) {
        const int mlo = m0 + wm * 32 + mt * 16 + g;
        const int mhi = mlo + 8;
        const bool vlo = (mlo < MTOT), vhi = (mhi < MTOT);
        float* plo = nullptr;
        float* phi = nullptr;
        if (vlo) { int bb = mlo / CHW; plo = out + (size_t)bb * COUT * CHW + (mlo - bb * CHW); }
        if (vhi) { int bb = mhi / CHW; phi = out + (size_t)bb * COUT * CHW + (mhi - bb * CHW); }
        #pragma unroll
        for (int nt = 0; nt < 8; nt++) {
            const int f0 = wn * 64 + nt * 8 + tg * 2;
            const float b0 = s_bias[f0], b1 = s_bias[f0 + 1];
            if (vlo) {
                plo[(size_t)f0 * CHW]       = acc[mt][nt][0] + b0;
                plo[(size_t)(f0 + 1) * CHW] = acc[mt][nt][1] + b1;
            }
            if (vhi) {
                phi[(size_t)f0 * CHW]       = acc[mt][nt][2] + b0;
                phi[(size_t)(f0 + 1) * CHW] = acc[mt][nt][3] + b1;
            }
        }
    }
    #undef LOAD_CHUNK
}

// ---------------------------------------------------------------------------
// Launch.
// ---------------------------------------------------------------------------
extern "C" void kernel_launch(void* const* d_in, const int* in_sizes, int n_in,
                              void* d_out, int out_size) {
    const float* x      = (const float*)d_in[0];
    const float* qw     = (const float*)d_in[1];
    const float* weight = (const float*)d_in[3];
    const float* bias   = (const float*)d_in[4];

    trig_kernel<<<2, 256>>>();
    dim3 tgrid((CHW + 31) / 32, CIN / 32, BSZ);
    transpose_kernel<<<tgrid, dim3(32, 8)>>>(x);
    wconv_kernel<<<(COUT * CK + 255) / 256, 256>>>(weight);

    wcomp_kernel<<<(NPAIR * NLON + 255) / 256, 256>>>(qw);
    runs_kernel<<<(NPAIR + 255) / 256, 256>>>();

    dim3 ggrid(NPT, NLAT, BSZ);
    gather_kernel<<<ggrid, 256>>>();

    const int dyn_bytes = NSTG * STGB;   // 81920
    cudaFuncSetAttribute(gemm_mma_kernel,
                         cudaFuncAttributeMaxDynamicSharedMemorySize, dyn_bytes);
    gemm_mma_kernel<<<MBLK, 256, dyn_bytes>>>(bias, (float*)d_out);
}